// round 16
// baseline (speedup 1.0000x reference)
#include <cuda_runtime.h>
#include <cuda_fp16.h>
#include <cstdint>

#define N_NODES 100000
#define N_EDGES 3200000
#define DIM     256

// ---------------------------------------------------------------------------
// Static device scratch (no runtime allocation allowed)
// ---------------------------------------------------------------------------
__device__ __half2 g_Yh[(size_t)N_NODES * (DIM / 2)];  // X @ W^T fp16 (51.2 MB)
__device__ uint2 g_edgeS[N_EDGES];                     // sorted (col, val) 25.6 MB
__device__ int   g_idx[N_EDGES];                       // per-edge slot within row
__device__ int   g_cnt[N_NODES];                       // per-row degree
__device__ int   g_off[N_NODES];                       // exclusive prefix

// ---------------------------------------------------------------------------
// Kernel A: zero counters
// ---------------------------------------------------------------------------
__global__ void __launch_bounds__(256) zero_kernel() {
    int i = blockIdx.x * blockDim.x + threadIdx.x;
    if (i < N_NODES) g_cnt[i] = 0;
}

// ---------------------------------------------------------------------------
// Kernel B: histogram of edge destination rows + record each edge's slot.
// ---------------------------------------------------------------------------
__global__ void __launch_bounds__(256) hist_kernel(const int* __restrict__ erow) {
    int i = blockIdx.x * blockDim.x + threadIdx.x;
    if (i < N_EDGES) g_idx[i] = atomicAdd(&g_cnt[erow[i]], 1);
}

// ---------------------------------------------------------------------------
// Kernel C: single-block chunked exclusive scan of g_cnt -> g_off
// ---------------------------------------------------------------------------
#define SCAN_THREADS 1024
#define SCAN_CHUNK   ((N_NODES + SCAN_THREADS - 1) / SCAN_THREADS)   // 98

__global__ void __launch_bounds__(SCAN_THREADS) scan_kernel() {
    __shared__ int sums[SCAN_THREADS];
    const int t     = threadIdx.x;
    const int start = t * SCAN_CHUNK;
    const int end   = min(start + SCAN_CHUNK, N_NODES);

    int s = 0;
    for (int i = start; i < end; i++) s += g_cnt[i];
    sums[t] = s;
    __syncthreads();

    for (int d = 1; d < SCAN_THREADS; d <<= 1) {
        int v = 0;
        if (t >= d) v = sums[t - d];
        __syncthreads();
        if (t >= d) sums[t] += v;
        __syncthreads();
    }

    int run = sums[t] - s;
    for (int i = start; i < end; i++) {
        g_off[i] = run;
        run += g_cnt[i];
    }
}

// ---------------------------------------------------------------------------
// Kernel D: scatter edges into row-sorted order — atomic-free.
// ---------------------------------------------------------------------------
__global__ void __launch_bounds__(256) sort_scatter_kernel(const int* __restrict__ erow,
                                                           const int* __restrict__ ecol,
                                                           const float* __restrict__ eval) {
    int i = blockIdx.x * blockDim.x + threadIdx.x;
    if (i >= N_EDGES) return;
    int p = g_off[erow[i]] + g_idx[i];
    g_edgeS[p] = make_uint2((unsigned)ecol[i], __float_as_uint(eval[i]));
}

// ---------------------------------------------------------------------------
// Kernel E: Y = fp16(X @ W^T) via tensor cores (mma.m16n8k16, fp32 accum).
// Block tile 128x128, K-tile 64 (2 iterations, 4 syncs total, MLP=16 loads).
// 8 warps: 2 (M) x 4 (N); warp tile 64x32.
// ---------------------------------------------------------------------------
#define GBM 128
#define GBN 128
#define GBK 64
#define TSTR 72   // smem row stride in halves (144 B): 8-row ldmatrix groups
                  // hit word-banks {0,4,...,28} — conflict-free

__device__ __forceinline__ uint32_t smem_u32(const void* p) {
    return (uint32_t)__cvta_generic_to_shared(p);
}

__global__ void __launch_bounds__(256) gemm_tc_kernel(const float* __restrict__ X,
                                                      const float* __restrict__ W,
                                                      int M) {
    __shared__ __half As[GBM * TSTR];   // 18.4 KB
    __shared__ __half Bs[GBN * TSTR];   // 18.4 KB

    const int tid  = threadIdx.x;
    const int warp = tid >> 5;
    const int lane = tid & 31;
    const int wm   = warp >> 2;
    const int wn   = warp & 3;
    const int bm0  = blockIdx.y * GBM;
    const int bn0  = blockIdx.x * GBN;

    float acc[4][4][4];
#pragma unroll
    for (int mf = 0; mf < 4; mf++)
#pragma unroll
        for (int nf = 0; nf < 4; nf++)
#pragma unroll
            for (int q = 0; q < 4; q++) acc[mf][nf][q] = 0.0f;

    // Load decomposition for a 128x64 tile: 128 rows x 16 float4 = 2048 float4,
    // 8 per thread. Thread t covers rows (t>>4) + 16*p, float4 col (t&15).
    const int lrow = tid >> 4;        // 0..15
    const int lf4  = tid & 15;        // 0..15 (float4 within 64-col row)

    for (int kk = 0; kk < DIM; kk += GBK) {
        // --- A tile: 128x64, fp32 -> fp16, 8 float4 per thread ---
#pragma unroll
        for (int p = 0; p < 8; p++) {
            int r  = lrow + p * 16;
            int gm = bm0 + r;
            float4 v = make_float4(0.f, 0.f, 0.f, 0.f);
            if (gm < M)
                v = *reinterpret_cast<const float4*>(X + (size_t)gm * DIM + kk + lf4 * 4);
            __half2 h0 = __floats2half2_rn(v.x, v.y);
            __half2 h1 = __floats2half2_rn(v.z, v.w);
            uint2 pk;
            pk.x = *reinterpret_cast<uint32_t*>(&h0);
            pk.y = *reinterpret_cast<uint32_t*>(&h1);
            *reinterpret_cast<uint2*>(&As[r * TSTR + lf4 * 4]) = pk;
        }
        // --- B tile: 128x64 (W rows; N=256 exact, no guard) ---
#pragma unroll
        for (int p = 0; p < 8; p++) {
            int r = lrow + p * 16;
            float4 v = *reinterpret_cast<const float4*>(W + (size_t)(bn0 + r) * DIM + kk + lf4 * 4);
            __half2 h0 = __floats2half2_rn(v.x, v.y);
            __half2 h1 = __floats2half2_rn(v.z, v.w);
            uint2 pk;
            pk.x = *reinterpret_cast<uint32_t*>(&h0);
            pk.y = *reinterpret_cast<uint32_t*>(&h1);
            *reinterpret_cast<uint2*>(&Bs[r * TSTR + lf4 * 4]) = pk;
        }
        __syncthreads();

#pragma unroll
        for (int ks = 0; ks < 4; ks++) {
            const int k0 = ks * 16;
            uint32_t a[4][4];
            uint32_t bfr[4][2];

#pragma unroll
            for (int mf = 0; mf < 4; mf++) {
                int row = wm * 64 + mf * 16 + (lane & 15);
                int col = k0 + (lane >> 4) * 8;
                uint32_t addr = smem_u32(&As[row * TSTR + col]);
                asm volatile("ldmatrix.sync.aligned.m8n8.x4.shared.b16 {%0,%1,%2,%3}, [%4];"
                             : "=r"(a[mf][0]), "=r"(a[mf][1]), "=r"(a[mf][2]), "=r"(a[mf][3])
                             : "r"(addr));
            }
#pragma unroll
            for (int nf = 0; nf < 4; nf++) {
                int row = wn * 32 + nf * 8 + (lane & 7);
                int col = k0 + ((lane >> 3) & 1) * 8;
                uint32_t addr = smem_u32(&Bs[row * TSTR + col]);
                asm volatile("ldmatrix.sync.aligned.m8n8.x2.shared.b16 {%0,%1}, [%2];"
                             : "=r"(bfr[nf][0]), "=r"(bfr[nf][1])
                             : "r"(addr));
            }
#pragma unroll
            for (int mf = 0; mf < 4; mf++)
#pragma unroll
                for (int nf = 0; nf < 4; nf++) {
                    asm volatile(
                        "mma.sync.aligned.m16n8k16.row.col.f32.f16.f16.f32 "
                        "{%0,%1,%2,%3}, {%4,%5,%6,%7}, {%8,%9}, {%0,%1,%2,%3};"
                        : "+f"(acc[mf][nf][0]), "+f"(acc[mf][nf][1]),
                          "+f"(acc[mf][nf][2]), "+f"(acc[mf][nf][3])
                        : "r"(a[mf][0]), "r"(a[mf][1]), "r"(a[mf][2]), "r"(a[mf][3]),
                          "r"(bfr[nf][0]), "r"(bfr[nf][1]));
                }
        }
        __syncthreads();
    }

    const int tr = lane >> 2;
    const int tc = lane & 3;
#pragma unroll
    for (int mf = 0; mf < 4; mf++)
#pragma unroll
        for (int nf = 0; nf < 4; nf++) {
            int col2 = (bn0 + wn * 32 + nf * 8) / 2 + tc;
            int r0 = bm0 + wm * 64 + mf * 16 + tr;
            if (r0 < M)
                g_Yh[(size_t)r0 * (DIM / 2) + col2] =
                    __floats2half2_rn(acc[mf][nf][0], acc[mf][nf][1]);
            int r1 = r0 + 8;
            if (r1 < M)
                g_Yh[(size_t)r1 * (DIM / 2) + col2] =
                    __floats2half2_rn(acc[mf][nf][2], acc[mf][nf][3]);
        }
}

// ---------------------------------------------------------------------------
// Kernel F: per-node gather-reduce (R6 form — proven local optimum).
// ---------------------------------------------------------------------------
__global__ void __launch_bounds__(256) gather_reduce_kernel(const float* __restrict__ b,
                                                            float* __restrict__ out) {
    const int warp = (blockIdx.x * blockDim.x + threadIdx.x) >> 5;
    const int lane = threadIdx.x & 31;
    if (warp >= N_NODES) return;

    const int start = g_off[warp];
    const int deg   = g_cnt[warp];

    float acc[8] = {0.f, 0.f, 0.f, 0.f, 0.f, 0.f, 0.f, 0.f};

    for (int base = 0; base < deg; base += 32) {
        const int rem = deg - base;
        const int lim = rem < 32 ? rem : 32;
        uint2 e = make_uint2(0u, 0u);
        if (lane < lim) e = g_edgeS[start + base + lane];
#pragma unroll 4
        for (int j = 0; j < lim; j++) {
            const int   cc = (int)__shfl_sync(0xffffffffu, e.x, j);
            const float vv = __uint_as_float(__shfl_sync(0xffffffffu, e.y, j));
            const uint4* src = reinterpret_cast<const uint4*>(g_Yh + (size_t)cc * (DIM / 2));
            uint4 p = src[lane];
            const __half2* h = reinterpret_cast<const __half2*>(&p);
#pragma unroll
            for (int q = 0; q < 4; q++) {
                float2 f = __half22float2(h[q]);
                acc[q * 2 + 0] = fmaf(vv, f.x, acc[q * 2 + 0]);
                acc[q * 2 + 1] = fmaf(vv, f.y, acc[q * 2 + 1]);
            }
        }
    }

    const float4* bv = reinterpret_cast<const float4*>(b);
    float4 b0 = bv[lane * 2];
    float4 b1 = bv[lane * 2 + 1];
    float4 o0 = make_float4(acc[0] + b0.x, acc[1] + b0.y, acc[2] + b0.z, acc[3] + b0.w);
    float4 o1 = make_float4(acc[4] + b1.x, acc[5] + b1.y, acc[6] + b1.z, acc[7] + b1.w);

    float4* dst = reinterpret_cast<float4*>(out + (size_t)warp * DIM);
    dst[lane * 2]     = o0;
    dst[lane * 2 + 1] = o1;
}

// ---------------------------------------------------------------------------
// Launch (single stream). Inputs: X, edge_row, edge_col, edge_val, W, b
// ---------------------------------------------------------------------------
extern "C" void kernel_launch(void* const* d_in, const int* in_sizes, int n_in,
                              void* d_out, int out_size) {
    const float* X    = (const float*)d_in[0];
    const int*   erow = (const int*)  d_in[1];
    const int*   ecol = (const int*)  d_in[2];
    const float* eval = (const float*)d_in[3];
    const float* W    = (const float*)d_in[4];
    const float* b    = (const float*)d_in[5];
    float*       out  = (float*)d_out;

    // 1) counting sort of edges by destination row (atomic-free scatter)
    zero_kernel<<<(N_NODES + 255) / 256, 256>>>();
    hist_kernel<<<(N_EDGES + 255) / 256, 256>>>(erow);
    scan_kernel<<<1, SCAN_THREADS>>>();
    sort_scatter_kernel<<<(N_EDGES + 255) / 256, 256>>>(erow, ecol, eval);

    // 2) Y = fp16(X @ W^T) on tensor cores (128x128 tile, K-tile 64)
    {
        dim3 grid(DIM / GBN, (N_NODES + GBM - 1) / GBM);
        gemm_tc_kernel<<<grid, 256>>>(X, W, N_NODES);
    }

    // 3) out[n] = b + sum val * Y[col]   (atomic-free)
    {
        int warps_per_block = 256 / 32;
        int blocks = (N_NODES + warps_per_block - 1) / warps_per_block;
        gather_reduce_kernel<<<blocks, 256>>>(b, out);
    }
}